// round 16
// baseline (speedup 1.0000x reference)
#include <cuda_runtime.h>
#include <cuda_bf16.h>
#include <cuda_pipeline.h>
#include <float.h>
#include <math.h>
#include <stdint.h>

// Problem constants
#define BB 2
#define NN 2048
#define DD 1024
#define HH 16
#define DH 64
#define DH3 (3*DH)           // 192
#define MROWS (BB*NN)        // 4096
#define QKVC (3*HH*DH)       // 3072
#define OUTC (HH*DH)         // 1024
#define K3 (3*DD)            // 3072

// GEMM tile config (raw mma, 3-stage pipeline)
#define GST 72
#define TSZ (128 * GST)
#define GS_STAGE (2 * TSZ)
#define GEMM_SMEM (3 * GS_STAGE * 2)   // 110592 bytes

// Flash config (round-15 proven): BM=128, BN=64, register P, V hi/lo planes.
#define SQ 200
#define SV 72
#define FOFF_K 51200
#define FOFF_V 102400
#define VSTAGE (128 * SV)
#define FLASH_SMEM (FOFF_V + 2 * VSTAGE * 2)   // 139264
#define KSTAGE (64 * SQ)

// merged split kernel ranges (8-float units)
#define NX8 (MROWS * DD / 8)     // 524288
#define NQ8 (QKVC * DD / 8)      // 393216
#define NO8 (DD * DD / 8)        // 131072

// ---------------- scratch ----------------
__device__ __align__(16) float g_qkv[(size_t)MROWS * QKVC];
__device__ __align__(16) __nv_bfloat16 g_q3[(size_t)BB * HH * NN * DH3];
__device__ __align__(16) __nv_bfloat16 g_k3[(size_t)BB * HH * NN * DH3];
__device__ __align__(16) __nv_bfloat16 g_v2[(size_t)BB * HH * 2 * NN * DH];
__device__ __align__(16) __nv_bfloat16 g_x3[(size_t)MROWS * K3];
__device__ __align__(16) __nv_bfloat16 g_wqkv3[(size_t)QKVC * K3];
__device__ __align__(16) __nv_bfloat16 g_att3[(size_t)MROWS * K3];
__device__ __align__(16) __nv_bfloat16 g_wout3[(size_t)DD * K3];

// ---------------- helpers ----------------
__device__ __forceinline__ uint32_t bfpack(__nv_bfloat16 a, __nv_bfloat16 b) {
    __nv_bfloat162 t;
    t.x = a; t.y = b;
    return *(uint32_t*)&t;
}

__device__ __forceinline__ float exp2_fast(float t) {
    t = fmaxf(t, -126.0f);
    const float fi = t + 12582912.0f;
    const float r = t - (fi - 12582912.0f);
    float p = 1.3333558e-3f;
    p = fmaf(p, r, 9.6181291e-3f);
    p = fmaf(p, r, 5.5504109e-2f);
    p = fmaf(p, r, 2.4022651e-1f);
    p = fmaf(p, r, 6.9314718e-1f);
    p = fmaf(p, r, 1.0f);
    const int ib = __float_as_int(fi) - 0x4B400000;
    return __int_as_float(__float_as_int(p) + (ib << 23));
}

// Raw PTX wrappers; braces in strings are octal-escaped (\173='{', \175='}').
__device__ __forceinline__ void mma16816(float* d, const uint32_t* a, const uint32_t* b) {
    asm volatile(
        "mma.sync.aligned.m16n8k16.row.col.f32.bf16.bf16.f32 "
        "\173%0,%1,%2,%3\175,\173%4,%5,%6,%7\175,\173%8,%9\175,\173%0,%1,%2,%3\175;"
        : "+f"(d[0]), "+f"(d[1]), "+f"(d[2]), "+f"(d[3])
        : "r"(a[0]), "r"(a[1]), "r"(a[2]), "r"(a[3]), "r"(b[0]), "r"(b[1]));
}
__device__ __forceinline__ void ldsm4(uint32_t* r, uint32_t addr) {
    asm volatile(
        "ldmatrix.sync.aligned.m8n8.x4.shared.b16 \173%0,%1,%2,%3\175,[%4];"
        : "=r"(r[0]), "=r"(r[1]), "=r"(r[2]), "=r"(r[3]) : "r"(addr));
}
__device__ __forceinline__ void ldsm4t(uint32_t* r, uint32_t addr) {
    asm volatile(
        "ldmatrix.sync.aligned.m8n8.x4.trans.shared.b16 \173%0,%1,%2,%3\175,[%4];"
        : "=r"(r[0]), "=r"(r[1]), "=r"(r[2]), "=r"(r[3]) : "r"(addr));
}

// ---------------- merged bf16 3-way split kernel ----------------
// pattern a: (hi,lo,hi)  for activations; pattern b: (hi,hi,lo) for weights.
__global__ void __launch_bounds__(256)
split3_all(const float* __restrict__ X, __nv_bfloat16* __restrict__ Yx,
           const float* __restrict__ Wq, __nv_bfloat16* __restrict__ Yq,
           const float* __restrict__ Wo, __nv_bfloat16* __restrict__ Yo)
{
    const int g = blockIdx.x * 256 + threadIdx.x;
    const float* src;
    __nv_bfloat16* dst;
    int i;
    bool pa;
    if (g < NX8)             { src = X;  dst = Yx; i = g;             pa = true;  }
    else if (g < NX8 + NQ8)  { src = Wq; dst = Yq; i = g - NX8;       pa = false; }
    else                     { src = Wo; dst = Yo; i = g - NX8 - NQ8; pa = false; }

    float f[8];
    *(float4*)&f[0] = *(const float4*)(src + (size_t)i * 8);
    *(float4*)&f[4] = *(const float4*)(src + (size_t)i * 8 + 4);
    __nv_bfloat16 o[24];
#pragma unroll
    for (int j = 0; j < 8; j++) {
        const __nv_bfloat16 hi = __float2bfloat16(f[j]);
        const __nv_bfloat16 lo = __float2bfloat16(f[j] - __bfloat162float(hi));
        if (pa) { o[3*j] = hi; o[3*j+1] = lo; o[3*j+2] = hi; }
        else    { o[3*j] = hi; o[3*j+1] = hi; o[3*j+2] = lo; }
    }
    uint4* d4 = (uint4*)(dst + (size_t)i * 24);
    const uint4* s4 = (const uint4*)o;
    d4[0] = s4[0]; d4[1] = s4[1]; d4[2] = s4[2];
}

// ---------------- GEMM stage loader ----------------
__device__ __forceinline__ void gemm_load_stage(
    __nv_bfloat16* s, const __nv_bfloat16* A, const __nv_bfloat16* B,
    int m0, int n0, int k0, int K, int tid)
{
#pragma unroll
    for (int p = 0; p < 8; p++) {
        const int c = tid + p * 256;
        const int row = (c >> 3) & 127;
        const int ch = c & 7;
        if (p < 4) {
            __pipeline_memcpy_async(s + row * GST + ch * 8,
                                    A + (size_t)(m0 + row) * K + k0 + ch * 8, 16);
        } else {
            __pipeline_memcpy_async(s + TSZ + row * GST + ch * 8,
                                    B + (size_t)(n0 + row) * K + k0 + ch * 8, 16);
        }
    }
    __pipeline_commit();
}

// ---------------- raw-mma GEMM with fragment double-buffering --------------
__global__ void __launch_bounds__(256, 2)
gemm_mma_nt(const __nv_bfloat16* __restrict__ A, const __nv_bfloat16* __restrict__ B,
            const float* __restrict__ bias, float* __restrict__ C,
            int M, int N, int K)
{
    extern __shared__ __nv_bfloat16 smem[];

    const int tid = threadIdx.x;
    const int lane = tid & 31;
    const int w = tid >> 5;
    const int wm = (w >> 2) * 64;
    const int wn = (w & 3) * 32;
    const int m0 = blockIdx.y * 128;
    const int n0 = blockIdx.x * 128;
    const int ntiles = K / 64;

    const uint32_t sb = (uint32_t)__cvta_generic_to_shared(smem);

    float acc[4][4][4];
#pragma unroll
    for (int mi = 0; mi < 4; mi++)
#pragma unroll
        for (int n8 = 0; n8 < 4; n8++)
#pragma unroll
            for (int e = 0; e < 4; e++) acc[mi][n8][e] = 0.f;

    gemm_load_stage(smem, A, B, m0, n0, 0, K, tid);
    gemm_load_stage(smem + GS_STAGE, A, B, m0, n0, 64, K, tid);

    const int a_r = lane & 15;
    const int a_c8 = (lane >> 4) * 8;
    const int b_r = ((lane >> 4) << 3) + (lane & 7);
    const int b_c8 = ((lane >> 3) & 1) * 8;

    for (int kt = 0; kt < ntiles; kt++) {
        if (kt + 1 < ntiles) __pipeline_wait_prior(1);
        else                 __pipeline_wait_prior(0);
        __syncthreads();
        if (kt + 2 < ntiles)
            gemm_load_stage(smem + ((kt + 2) % 3) * GS_STAGE, A, B, m0, n0,
                            (kt + 2) * 64, K, tid);

        const uint32_t asb = sb + (uint32_t)((kt % 3) * GS_STAGE * 2);
        const uint32_t bsb = asb + (uint32_t)(TSZ * 2);

        uint32_t a[2][4][4];
        uint32_t b[2][2][4];
        // preload kk=0 fragments
#pragma unroll
        for (int mi = 0; mi < 4; mi++)
            ldsm4(a[0][mi], asb + (uint32_t)(((wm + mi * 16 + a_r) * GST + a_c8) * 2));
#pragma unroll
        for (int ni = 0; ni < 2; ni++)
            ldsm4(b[0][ni], bsb + (uint32_t)(((wn + ni * 16 + b_r) * GST + b_c8) * 2));

#pragma unroll
        for (int kk = 0; kk < 4; kk++) {
            const int cur = kk & 1;
            const int nxt = cur ^ 1;
            if (kk < 3) {
#pragma unroll
                for (int mi = 0; mi < 4; mi++)
                    ldsm4(a[nxt][mi], asb + (uint32_t)(((wm + mi * 16 + a_r) * GST +
                                                        (kk + 1) * 16 + a_c8) * 2));
#pragma unroll
                for (int ni = 0; ni < 2; ni++)
                    ldsm4(b[nxt][ni], bsb + (uint32_t)(((wn + ni * 16 + b_r) * GST +
                                                        (kk + 1) * 16 + b_c8) * 2));
            }
#pragma unroll
            for (int mi = 0; mi < 4; mi++)
#pragma unroll
                for (int ni = 0; ni < 2; ni++) {
                    mma16816(acc[mi][2 * ni], a[cur][mi], b[cur][ni]);
                    mma16816(acc[mi][2 * ni + 1], a[cur][mi], b[cur][ni] + 2);
                }
        }
    }

    const int r0 = lane >> 2;
    const int c0 = 2 * (lane & 3);
#pragma unroll
    for (int mi = 0; mi < 4; mi++) {
#pragma unroll
        for (int n8 = 0; n8 < 4; n8++) {
            const int row = m0 + wm + mi * 16 + r0;
            const int col = n0 + wn + n8 * 8 + c0;
            float b0 = 0.f, b1 = 0.f;
            if (bias) { b0 = bias[col]; b1 = bias[col + 1]; }
            *(float2*)(C + (size_t)row * N + col) =
                make_float2(acc[mi][n8][0] + b0, acc[mi][n8][1] + b1);
            *(float2*)(C + (size_t)(row + 8) * N + col) =
                make_float2(acc[mi][n8][2] + b0, acc[mi][n8][3] + b1);
        }
    }
}

// ---------------- RoPE + split: Q3/K3 [bh,N,192], V2 [bh,2,N,64] -----------
__global__ void __launch_bounds__(256)
rope3_kernel(const float* __restrict__ qkv, const float* __restrict__ rope,
             __nv_bfloat16* __restrict__ Q3, __nv_bfloat16* __restrict__ K3g,
             __nv_bfloat16* __restrict__ V2)
{
    const int idx = blockIdx.x * 256 + threadIdx.x;
    if (idx >= BB * NN * HH * 32) return;
    const int p2 = (idx & 31) << 1;
    const int h  = (idx >> 5) & (HH - 1);
    const int n  = (idx >> 9) & (NN - 1);
    const int b  = idx >> 20;

    const float f0 = rope[n * DH + p2];
    const float f1 = rope[n * DH + p2 + 1];
    float s0, c0, s1, c1;
    sincosf(f0, &s0, &c0);
    sincosf(f1, &s1, &c1);

    const size_t row = ((size_t)b * NN + n) * QKVC;
    const float2 q = *(const float2*)(qkv + row + h * DH + p2);
    const float2 k = *(const float2*)(qkv + row + OUTC + h * DH + p2);
    const float2 v = *(const float2*)(qkv + row + 2 * OUTC + h * DH + p2);

    const float SCALE = 0.125f;
    float qx = (q.x * c0 - q.y * s0) * SCALE;
    float qy = (q.y * c1 + q.x * s1) * SCALE;
    float kx = k.x * c0 - k.y * s0;
    float ky = k.y * c1 + k.x * s1;
    float vx = v.x * c0 - v.y * s0;
    float vy = v.y * c1 + v.x * s1;

    const __nv_bfloat16 qh0 = __float2bfloat16(qx);
    const __nv_bfloat16 ql0 = __float2bfloat16(qx - __bfloat162float(qh0));
    const __nv_bfloat16 qh1 = __float2bfloat16(qy);
    const __nv_bfloat16 ql1 = __float2bfloat16(qy - __bfloat162float(qh1));
    const __nv_bfloat16 kh0 = __float2bfloat16(kx);
    const __nv_bfloat16 kl0 = __float2bfloat16(kx - __bfloat162float(kh0));
    const __nv_bfloat16 kh1 = __float2bfloat16(ky);
    const __nv_bfloat16 kl1 = __float2bfloat16(ky - __bfloat162float(kh1));
    const __nv_bfloat16 vh0 = __float2bfloat16(vx);
    const __nv_bfloat16 vl0 = __float2bfloat16(vx - __bfloat162float(vh0));
    const __nv_bfloat16 vh1 = __float2bfloat16(vy);
    const __nv_bfloat16 vl1 = __float2bfloat16(vy - __bfloat162float(vh1));

    const int bh = b * HH + h;
    uint32_t* qp = (uint32_t*)(Q3 + ((size_t)bh * NN + n) * DH3 + 3 * p2);
    qp[0] = bfpack(qh0, ql0);
    qp[1] = bfpack(qh0, qh1);
    qp[2] = bfpack(ql1, qh1);
    uint32_t* kp = (uint32_t*)(K3g + ((size_t)bh * NN + n) * DH3 + 3 * p2);
    kp[0] = bfpack(kh0, kh0);
    kp[1] = bfpack(kl0, kh1);
    kp[2] = bfpack(kh1, kl1);
    uint32_t* vp = (uint32_t*)(V2 + ((size_t)bh * 2 * NN + n) * DH + p2);
    vp[0] = bfpack(vh0, vh1);
    vp[(size_t)NN * DH / 2] = bfpack(vl0, vl1);
}

// ---------------- flash K/V stage prefetch ----------------
__device__ __forceinline__ void flash_prefetch(
    __nv_bfloat16* ks, __nv_bfloat16* vsm,
    const __nv_bfloat16* Kbase, const __nv_bfloat16* Vbase,
    int kv0, int tid)
{
#pragma unroll
    for (int p = 0; p < 6; p++) {
        const int c = tid + p * 256;
        const int r = c / 24;
        const int col = (c % 24) * 8;
        __pipeline_memcpy_async(ks + r * SQ + col,
                                Kbase + (size_t)(kv0 + r) * DH3 + col, 16);
    }
#pragma unroll
    for (int p = 0; p < 4; p++) {
        const int c = tid + p * 256;
        const int r = c >> 3;
        const int col = (c & 7) * 8;
        const int plane = r >> 6;
        const int n = r & 63;
        __pipeline_memcpy_async(vsm + r * SV + col,
                                Vbase + (size_t)plane * NN * DH +
                                (size_t)(kv0 + n) * DH + col, 16);
    }
    __pipeline_commit();
}

// ---------------- Flash attention: register mma, register P ----------------
__global__ void __launch_bounds__(256)
flash_mma(const __nv_bfloat16* __restrict__ Q3,
          const __nv_bfloat16* __restrict__ Kg3,
          const __nv_bfloat16* __restrict__ Vg2,
          __nv_bfloat16* __restrict__ ATT3)
{
    extern __shared__ char fsm[];
    __nv_bfloat16* q3s = (__nv_bfloat16*)fsm;
    __nv_bfloat16* k3s = (__nv_bfloat16*)(fsm + FOFF_K);
    __nv_bfloat16* v2s = (__nv_bfloat16*)(fsm + FOFF_V);

    const int tid = threadIdx.x;
    const int w = tid >> 5;
    const int lane = tid & 31;
    const int qt = (int)gridDim.x - 1 - (int)blockIdx.x;   // heavy first
    const int bh = blockIdx.y;
    const int q0 = qt * 128;

    const __nv_bfloat16* Qbase = Q3 + ((size_t)bh * NN + q0) * DH3;
    const __nv_bfloat16* Kbase = Kg3 + (size_t)bh * NN * DH3;
    const __nv_bfloat16* Vbase = Vg2 + (size_t)bh * 2 * NN * DH;

    const uint32_t qsb = (uint32_t)__cvta_generic_to_shared(q3s);
    const uint32_t ksb = (uint32_t)__cvta_generic_to_shared(k3s);
    const uint32_t vsb = (uint32_t)__cvta_generic_to_shared(v2s);

    flash_prefetch(k3s, v2s, Kbase, Vbase, 0, tid);

#pragma unroll
    for (int p = 0; p < 12; p++) {
        const int c = tid + p * 256;
        const int r = c / 24;
        const int col = (c % 24) * 8;
        *(uint4*)(q3s + r * SQ + col) =
            *(const uint4*)(Qbase + (size_t)r * DH3 + col);
    }

    const int r0 = lane >> 2;
    const int cq = lane & 3;
    const int mrow = 16 * w;
    const int grow0 = q0 + mrow + r0;
    const int grow1 = grow0 + 8;

    const int a_row = mrow + (lane & 15);
    const int a_col8 = (lane >> 4) * 8;
    const int b_rowk = ((lane >> 4) << 3) + (lane & 7);
    const int b_colk8 = ((lane >> 3) & 1) * 8;
    const int v_rowk = lane & 15;
    const int v_col8 = (lane >> 4) * 8;

    float o[8][4];
#pragma unroll
    for (int d = 0; d < 8; d++)
#pragma unroll
        for (int e = 0; e < 4; e++) o[d][e] = 0.f;
    float m0 = -1e30f, m1 = -1e30f, l0 = 0.f, l1 = 0.f;

    const int last = 2 * qt + 1;
    for (int kt = 0; kt <= last; kt++) {
        const int st = kt & 1;
        const int kv0 = kt * 64;

        __pipeline_wait_prior(0);
        __syncthreads();
        if (kt < last)
            flash_prefetch(k3s + (st ^ 1) * KSTAGE, v2s + (st ^ 1) * VSTAGE,
                           Kbase, Vbase, kv0 + 64, tid);

        const bool active = (kv0 <= q0 + mrow + 15);
        const uint32_t kst = ksb + (uint32_t)(st * KSTAGE * 2);
        const uint32_t vst = vsb + (uint32_t)(st * VSTAGE * 2);

        if (active) {
            float sacc[8][4];
#pragma unroll
            for (int d = 0; d < 8; d++)
#pragma unroll
                for (int e = 0; e < 4; e++) sacc[d][e] = 0.f;

#pragma unroll
            for (int kk = 0; kk < 12; kk++) {
                uint32_t a[4];
                ldsm4(a, qsb + (uint32_t)((a_row * SQ + kk * 16 + a_col8) * 2));
#pragma unroll
                for (int np = 0; np < 4; np++) {
                    uint32_t b[4];
                    ldsm4(b, kst + (uint32_t)(((np * 16 + b_rowk) * SQ +
                                               kk * 16 + b_colk8) * 2));
                    mma16816(sacc[2 * np], a, b);
                    mma16816(sacc[2 * np + 1], a, b + 2);
                }
            }

            if (kv0 + 63 > grow0) {
#pragma unroll
                for (int d = 0; d < 8; d++) {
                    const int col = kv0 + d * 8 + 2 * cq;
                    if (col > grow0)     sacc[d][0] = -1e30f;
                    if (col + 1 > grow0) sacc[d][1] = -1e30f;
                    if (col > grow1)     sacc[d][2] = -1e30f;
                    if (col + 1 > grow1) sacc[d][3] = -1e30f;
                }
            }
            float rm0 = sacc[0][0], rm1 = sacc[0][2];
#pragma unroll
            for (int d = 0; d < 8; d++) {
                rm0 = fmaxf(rm0, fmaxf(sacc[d][0], sacc[d][1]));
                rm1 = fmaxf(rm1, fmaxf(sacc[d][2], sacc[d][3]));
            }
            rm0 = fmaxf(rm0, __shfl_xor_sync(0xffffffffu, rm0, 1));
            rm0 = fmaxf(rm0, __shfl_xor_sync(0xffffffffu, rm0, 2));
            rm1 = fmaxf(rm1, __shfl_xor_sync(0xffffffffu, rm1, 1));
            rm1 = fmaxf(rm1, __shfl_xor_sync(0xffffffffu, rm1, 2));
            const float mn0 = fmaxf(m0, rm0);
            const float mn1 = fmaxf(m1, rm1);
            const float al0 = exp2_fast((m0 - mn0) * 1.4426950f);
            const float al1 = exp2_fast((m1 - mn1) * 1.4426950f);
            m0 = mn0; m1 = mn1;

            uint32_t phT[8], phB[8], plT[8], plB[8];
            float rs0 = 0.f, rs1 = 0.f;
#pragma unroll
            for (int d = 0; d < 8; d++) {
                const float p00 = exp2_fast((sacc[d][0] - mn0) * 1.4426950f);
                const float p01 = exp2_fast((sacc[d][1] - mn0) * 1.4426950f);
                const float p10 = exp2_fast((sacc[d][2] - mn1) * 1.4426950f);
                const float p11 = exp2_fast((sacc[d][3] - mn1) * 1.4426950f);
                rs0 += p00 + p01;
                rs1 += p10 + p11;
                const __nv_bfloat16 h00 = __float2bfloat16(p00);
                const __nv_bfloat16 g00 = __float2bfloat16(p00 - __bfloat162float(h00));
                const __nv_bfloat16 h01 = __float2bfloat16(p01);
                const __nv_bfloat16 g01 = __float2bfloat16(p01 - __bfloat162float(h01));
                const __nv_bfloat16 h10 = __float2bfloat16(p10);
                const __nv_bfloat16 g10 = __float2bfloat16(p10 - __bfloat162float(h10));
                const __nv_bfloat16 h11 = __float2bfloat16(p11);
                const __nv_bfloat16 g11 = __float2bfloat16(p11 - __bfloat162float(h11));
                phT[d] = bfpack(h00, h01);
                phB[d] = bfpack(h10, h11);
                plT[d] = bfpack(g00, g01);
                plB[d] = bfpack(g10, g11);
            }
            rs0 += __shfl_xor_sync(0xffffffffu, rs0, 1);
            rs0 += __shfl_xor_sync(0xffffffffu, rs0, 2);
            rs1 += __shfl_xor_sync(0xffffffffu, rs1, 1);
            rs1 += __shfl_xor_sync(0xffffffffu, rs1, 2);
            l0 = l0 * al0 + rs0;
            l1 = l1 * al1 + rs1;

#pragma unroll
            for (int d = 0; d < 8; d++) {
                o[d][0] *= al0; o[d][1] *= al0;
                o[d][2] *= al1; o[d][3] *= al1;
            }

#pragma unroll
            for (int kk = 0; kk < 4; kk++) {
                const uint32_t ah[4] = {phT[2*kk], phB[2*kk], phT[2*kk+1], phB[2*kk+1]};
                const uint32_t al_[4] = {plT[2*kk], plB[2*kk], plT[2*kk+1], plB[2*kk+1]};
#pragma unroll
                for (int np = 0; np < 4; np++) {
                    uint32_t vh[4], vl[4];
                    ldsm4t(vh, vst + (uint32_t)(((kk * 16 + v_rowk) * SV +
                                                 np * 16 + v_col8) * 2));
                    ldsm4t(vl, vst + (uint32_t)(((64 + kk * 16 + v_rowk) * SV +
                                                 np * 16 + v_col8) * 2));
                    mma16816(o[2 * np], ah, vh);
                    mma16816(o[2 * np + 1], ah, vh + 2);
                    mma16816(o[2 * np], al_, vh);
                    mma16816(o[2 * np + 1], al_, vh + 2);
                    mma16816(o[2 * np], ah, vl);
                    mma16816(o[2 * np + 1], ah, vl + 2);
                }
            }
        }
    }

    // epilogue: write att3 directly (pattern a: hi,lo,hi)
    {
        const int b = bh >> 4;
        const int h = bh & 15;
        const float inv0 = 1.f / l0;
        const float inv1 = 1.f / l1;
        char* orow0 = (char*)ATT3 + (size_t)(b * NN + grow0) * (K3 * 2) +
                      (h * 192 + 6 * cq) * 2;
        char* orow1 = orow0 + (size_t)8 * (K3 * 2);
#pragma unroll
        for (int d = 0; d < 8; d++) {
            const float e00 = o[d][0] * inv0;
            const float e01 = o[d][1] * inv0;
            const float e10 = o[d][2] * inv1;
            const float e11 = o[d][3] * inv1;
            const __nv_bfloat16 h00 = __float2bfloat16(e00);
            const __nv_bfloat16 g00 = __float2bfloat16(e00 - __bfloat162float(h00));
            const __nv_bfloat16 h01 = __float2bfloat16(e01);
            const __nv_bfloat16 g01 = __float2bfloat16(e01 - __bfloat162float(h01));
            const __nv_bfloat16 h10 = __float2bfloat16(e10);
            const __nv_bfloat16 g10 = __float2bfloat16(e10 - __bfloat162float(h10));
            const __nv_bfloat16 h11 = __float2bfloat16(e11);
            const __nv_bfloat16 g11 = __float2bfloat16(e11 - __bfloat162float(h11));
            uint32_t* w0 = (uint32_t*)(orow0 + 48 * d);
            w0[0] = bfpack(h00, g00);
            w0[1] = bfpack(h00, h01);
            w0[2] = bfpack(g01, h01);
            uint32_t* w1 = (uint32_t*)(orow1 + 48 * d);
            w1[0] = bfpack(h10, g10);
            w1[1] = bfpack(h10, h11);
            w1[2] = bfpack(g11, h11);
        }
    }
}

// ---------------- launch ----------------
extern "C" void kernel_launch(void* const* d_in, const int* in_sizes, int n_in,
                              void* d_out, int out_size)
{
    const float* x            = (const float*)d_in[0];
    const float* rope         = (const float*)d_in[2];
    const float* Wqkv         = (const float*)d_in[3];
    const float* Wout         = (const float*)d_in[4];
    const float* bout         = (const float*)d_in[5];
    float* out = (float*)d_out;

    float *qkv;
    __nv_bfloat16 *q3, *k3, *v2, *x3, *wqkv3, *att3, *wout3;
    cudaGetSymbolAddress((void**)&qkv, g_qkv);
    cudaGetSymbolAddress((void**)&q3,  g_q3);
    cudaGetSymbolAddress((void**)&k3,  g_k3);
    cudaGetSymbolAddress((void**)&v2,  g_v2);
    cudaGetSymbolAddress((void**)&x3,    g_x3);
    cudaGetSymbolAddress((void**)&wqkv3, g_wqkv3);
    cudaGetSymbolAddress((void**)&att3,  g_att3);
    cudaGetSymbolAddress((void**)&wout3, g_wout3);

    cudaFuncSetAttribute(gemm_mma_nt, cudaFuncAttributeMaxDynamicSharedMemorySize,
                         GEMM_SMEM);
    cudaFuncSetAttribute(flash_mma, cudaFuncAttributeMaxDynamicSharedMemorySize,
                         FLASH_SMEM);

    // merged splits (x pattern-a; Wqkv, Wout pattern-b)
    split3_all<<<(NX8 + NQ8 + NO8) / 256, 256>>>(x, x3, Wqkv, wqkv3, Wout, wout3);

    // 1) qkv = x @ Wqkv^T
    gemm_mma_nt<<<dim3(QKVC / 128, MROWS / 128), 256, GEMM_SMEM>>>(
        x3, wqkv3, (const float*)0, qkv, MROWS, QKVC, K3);

    // 2) RoPE + split -> Q3, K3, V2 (hi/lo planes)
    rope3_kernel<<<(BB * NN * HH * 32 + 255) / 256, 256>>>(qkv, rope, q3, k3, v2);

    // 3) causal flash attention -> att3 (pre-split for out-proj)
    flash_mma<<<dim3(NN / 128, BB * HH), 256, FLASH_SMEM>>>(q3, k3, v2, att3);

    // 4) out = att @ Wout^T + bias (fused)
    gemm_mma_nt<<<dim3(OUTC / 128, MROWS / 128), 256, GEMM_SMEM>>>(
        att3, wout3, bout, out, MROWS, OUTC, K3);
}

// round 17
// speedup vs baseline: 1.0649x; 1.0649x over previous
#include <cuda_runtime.h>
#include <cuda_bf16.h>
#include <cuda_pipeline.h>
#include <float.h>
#include <math.h>
#include <stdint.h>

// Problem constants
#define BB 2
#define NN 2048
#define DD 1024
#define HH 16
#define DH 64
#define DH3 (3*DH)           // 192
#define MROWS (BB*NN)        // 4096
#define QKVC (3*HH*DH)       // 3072
#define OUTC (HH*DH)         // 1024
#define K3 (3*DD)            // 3072

// GEMM tile config (round-15 proven)
#define GST 72
#define TSZ (128 * GST)
#define GS_STAGE (2 * TSZ)
#define GEMM_SMEM (3 * GS_STAGE * 2)   // 110592 bytes

// Flash config: BM=128, BN=64, register P (in-place over sacc),
// single-stage K/V with phase-overlapped prefetch, 2 blocks/SM.
#define SQ 200
#define SV 72
#define FOFF_K 51200                   // q3s: 128*200*2
#define FOFF_V 76800                   // k3s: 64*200*2 = 25600
#define FLASH_SMEM 95232               // + v2s: 128*72*2 = 18432

// merged split kernel ranges (8-float units)
#define NX8 (MROWS * DD / 8)
#define NQ8 (QKVC * DD / 8)
#define NO8 (DD * DD / 8)

// ---------------- scratch ----------------
__device__ __align__(16) float g_qkv[(size_t)MROWS * QKVC];
__device__ __align__(16) __nv_bfloat16 g_q3[(size_t)BB * HH * NN * DH3];
__device__ __align__(16) __nv_bfloat16 g_k3[(size_t)BB * HH * NN * DH3];
__device__ __align__(16) __nv_bfloat16 g_v2[(size_t)BB * HH * 2 * NN * DH];
__device__ __align__(16) __nv_bfloat16 g_x3[(size_t)MROWS * K3];
__device__ __align__(16) __nv_bfloat16 g_wqkv3[(size_t)QKVC * K3];
__device__ __align__(16) __nv_bfloat16 g_att3[(size_t)MROWS * K3];
__device__ __align__(16) __nv_bfloat16 g_wout3[(size_t)DD * K3];

// ---------------- helpers ----------------
__device__ __forceinline__ uint32_t bfpack(__nv_bfloat16 a, __nv_bfloat16 b) {
    __nv_bfloat162 t;
    t.x = a; t.y = b;
    return *(uint32_t*)&t;
}

__device__ __forceinline__ float exp2_fast(float t) {
    t = fmaxf(t, -126.0f);
    const float fi = t + 12582912.0f;
    const float r = t - (fi - 12582912.0f);
    float p = 1.3333558e-3f;
    p = fmaf(p, r, 9.6181291e-3f);
    p = fmaf(p, r, 5.5504109e-2f);
    p = fmaf(p, r, 2.4022651e-1f);
    p = fmaf(p, r, 6.9314718e-1f);
    p = fmaf(p, r, 1.0f);
    const int ib = __float_as_int(fi) - 0x4B400000;
    return __int_as_float(__float_as_int(p) + (ib << 23));
}

// Raw PTX wrappers; braces in strings are octal-escaped (\173='{', \175='}').
__device__ __forceinline__ void mma16816(float* d, const uint32_t* a, const uint32_t* b) {
    asm volatile(
        "mma.sync.aligned.m16n8k16.row.col.f32.bf16.bf16.f32 "
        "\173%0,%1,%2,%3\175,\173%4,%5,%6,%7\175,\173%8,%9\175,\173%0,%1,%2,%3\175;"
        : "+f"(d[0]), "+f"(d[1]), "+f"(d[2]), "+f"(d[3])
        : "r"(a[0]), "r"(a[1]), "r"(a[2]), "r"(a[3]), "r"(b[0]), "r"(b[1]));
}
__device__ __forceinline__ void ldsm4(uint32_t* r, uint32_t addr) {
    asm volatile(
        "ldmatrix.sync.aligned.m8n8.x4.shared.b16 \173%0,%1,%2,%3\175,[%4];"
        : "=r"(r[0]), "=r"(r[1]), "=r"(r[2]), "=r"(r[3]) : "r"(addr));
}
__device__ __forceinline__ void ldsm4t(uint32_t* r, uint32_t addr) {
    asm volatile(
        "ldmatrix.sync.aligned.m8n8.x4.trans.shared.b16 \173%0,%1,%2,%3\175,[%4];"
        : "=r"(r[0]), "=r"(r[1]), "=r"(r[2]), "=r"(r[3]) : "r"(addr));
}

// ---------------- merged bf16 3-way split kernel ----------------
__global__ void __launch_bounds__(256)
split3_all(const float* __restrict__ X, __nv_bfloat16* __restrict__ Yx,
           const float* __restrict__ Wq, __nv_bfloat16* __restrict__ Yq,
           const float* __restrict__ Wo, __nv_bfloat16* __restrict__ Yo)
{
    const int g = blockIdx.x * 256 + threadIdx.x;
    const float* src;
    __nv_bfloat16* dst;
    int i;
    bool pa;
    if (g < NX8)             { src = X;  dst = Yx; i = g;             pa = true;  }
    else if (g < NX8 + NQ8)  { src = Wq; dst = Yq; i = g - NX8;       pa = false; }
    else                     { src = Wo; dst = Yo; i = g - NX8 - NQ8; pa = false; }

    float f[8];
    *(float4*)&f[0] = *(const float4*)(src + (size_t)i * 8);
    *(float4*)&f[4] = *(const float4*)(src + (size_t)i * 8 + 4);
    __nv_bfloat16 o[24];
#pragma unroll
    for (int j = 0; j < 8; j++) {
        const __nv_bfloat16 hi = __float2bfloat16(f[j]);
        const __nv_bfloat16 lo = __float2bfloat16(f[j] - __bfloat162float(hi));
        if (pa) { o[3*j] = hi; o[3*j+1] = lo; o[3*j+2] = hi; }
        else    { o[3*j] = hi; o[3*j+1] = hi; o[3*j+2] = lo; }
    }
    uint4* d4 = (uint4*)(dst + (size_t)i * 24);
    const uint4* s4 = (const uint4*)o;
    d4[0] = s4[0]; d4[1] = s4[1]; d4[2] = s4[2];
}

// ---------------- GEMM stage loader ----------------
__device__ __forceinline__ void gemm_load_stage(
    __nv_bfloat16* s, const __nv_bfloat16* A, const __nv_bfloat16* B,
    int m0, int n0, int k0, int K, int tid)
{
#pragma unroll
    for (int p = 0; p < 8; p++) {
        const int c = tid + p * 256;
        const int row = (c >> 3) & 127;
        const int ch = c & 7;
        if (p < 4) {
            __pipeline_memcpy_async(s + row * GST + ch * 8,
                                    A + (size_t)(m0 + row) * K + k0 + ch * 8, 16);
        } else {
            __pipeline_memcpy_async(s + TSZ + row * GST + ch * 8,
                                    B + (size_t)(n0 + row) * K + k0 + ch * 8, 16);
        }
    }
    __pipeline_commit();
}

// ---------------- raw-mma GEMM (round-15 proven) ----------------
__global__ void __launch_bounds__(256, 2)
gemm_mma_nt(const __nv_bfloat16* __restrict__ A, const __nv_bfloat16* __restrict__ B,
            const float* __restrict__ bias, float* __restrict__ C,
            int M, int N, int K)
{
    extern __shared__ __nv_bfloat16 smem[];

    const int tid = threadIdx.x;
    const int lane = tid & 31;
    const int w = tid >> 5;
    const int wm = (w >> 2) * 64;
    const int wn = (w & 3) * 32;
    const int m0 = blockIdx.y * 128;
    const int n0 = blockIdx.x * 128;
    const int ntiles = K / 64;

    const uint32_t sb = (uint32_t)__cvta_generic_to_shared(smem);

    float acc[4][4][4];
#pragma unroll
    for (int mi = 0; mi < 4; mi++)
#pragma unroll
        for (int n8 = 0; n8 < 4; n8++)
#pragma unroll
            for (int e = 0; e < 4; e++) acc[mi][n8][e] = 0.f;

    gemm_load_stage(smem, A, B, m0, n0, 0, K, tid);
    gemm_load_stage(smem + GS_STAGE, A, B, m0, n0, 64, K, tid);

    const int a_r = lane & 15;
    const int a_c8 = (lane >> 4) * 8;
    const int b_r = ((lane >> 4) << 3) + (lane & 7);
    const int b_c8 = ((lane >> 3) & 1) * 8;

    for (int kt = 0; kt < ntiles; kt++) {
        if (kt + 1 < ntiles) __pipeline_wait_prior(1);
        else                 __pipeline_wait_prior(0);
        __syncthreads();
        if (kt + 2 < ntiles)
            gemm_load_stage(smem + ((kt + 2) % 3) * GS_STAGE, A, B, m0, n0,
                            (kt + 2) * 64, K, tid);

        const uint32_t asb = sb + (uint32_t)((kt % 3) * GS_STAGE * 2);
        const uint32_t bsb = asb + (uint32_t)(TSZ * 2);
#pragma unroll
        for (int kk = 0; kk < 4; kk++) {
            uint32_t a[4][4];
            uint32_t b[2][4];
#pragma unroll
            for (int mi = 0; mi < 4; mi++)
                ldsm4(a[mi], asb + (uint32_t)(((wm + mi * 16 + a_r) * GST +
                                               kk * 16 + a_c8) * 2));
#pragma unroll
            for (int ni = 0; ni < 2; ni++)
                ldsm4(b[ni], bsb + (uint32_t)(((wn + ni * 16 + b_r) * GST +
                                               kk * 16 + b_c8) * 2));
#pragma unroll
            for (int mi = 0; mi < 4; mi++)
#pragma unroll
                for (int ni = 0; ni < 2; ni++) {
                    mma16816(acc[mi][2 * ni], a[mi], b[ni]);
                    mma16816(acc[mi][2 * ni + 1], a[mi], b[ni] + 2);
                }
        }
    }

    const int r0 = lane >> 2;
    const int c0 = 2 * (lane & 3);
#pragma unroll
    for (int mi = 0; mi < 4; mi++) {
#pragma unroll
        for (int n8 = 0; n8 < 4; n8++) {
            const int row = m0 + wm + mi * 16 + r0;
            const int col = n0 + wn + n8 * 8 + c0;
            float b0 = 0.f, b1 = 0.f;
            if (bias) { b0 = bias[col]; b1 = bias[col + 1]; }
            *(float2*)(C + (size_t)row * N + col) =
                make_float2(acc[mi][n8][0] + b0, acc[mi][n8][1] + b1);
            *(float2*)(C + (size_t)(row + 8) * N + col) =
                make_float2(acc[mi][n8][2] + b0, acc[mi][n8][3] + b1);
        }
    }
}

// ---------------- RoPE + split: Q3/K3 [bh,N,192], V2 [bh,2,N,64] -----------
__global__ void __launch_bounds__(256)
rope3_kernel(const float* __restrict__ qkv, const float* __restrict__ rope,
             __nv_bfloat16* __restrict__ Q3, __nv_bfloat16* __restrict__ K3g,
             __nv_bfloat16* __restrict__ V2)
{
    const int idx = blockIdx.x * 256 + threadIdx.x;
    if (idx >= BB * NN * HH * 32) return;
    const int p2 = (idx & 31) << 1;
    const int h  = (idx >> 5) & (HH - 1);
    const int n  = (idx >> 9) & (NN - 1);
    const int b  = idx >> 20;

    const float f0 = rope[n * DH + p2];
    const float f1 = rope[n * DH + p2 + 1];
    float s0, c0, s1, c1;
    sincosf(f0, &s0, &c0);
    sincosf(f1, &s1, &c1);

    const size_t row = ((size_t)b * NN + n) * QKVC;
    const float2 q = *(const float2*)(qkv + row + h * DH + p2);
    const float2 k = *(const float2*)(qkv + row + OUTC + h * DH + p2);
    const float2 v = *(const float2*)(qkv + row + 2 * OUTC + h * DH + p2);

    const float SCALE = 0.125f;
    float qx = (q.x * c0 - q.y * s0) * SCALE;
    float qy = (q.y * c1 + q.x * s1) * SCALE;
    float kx = k.x * c0 - k.y * s0;
    float ky = k.y * c1 + k.x * s1;
    float vx = v.x * c0 - v.y * s0;
    float vy = v.y * c1 + v.x * s1;

    const __nv_bfloat16 qh0 = __float2bfloat16(qx);
    const __nv_bfloat16 ql0 = __float2bfloat16(qx - __bfloat162float(qh0));
    const __nv_bfloat16 qh1 = __float2bfloat16(qy);
    const __nv_bfloat16 ql1 = __float2bfloat16(qy - __bfloat162float(qh1));
    const __nv_bfloat16 kh0 = __float2bfloat16(kx);
    const __nv_bfloat16 kl0 = __float2bfloat16(kx - __bfloat162float(kh0));
    const __nv_bfloat16 kh1 = __float2bfloat16(ky);
    const __nv_bfloat16 kl1 = __float2bfloat16(ky - __bfloat162float(kh1));
    const __nv_bfloat16 vh0 = __float2bfloat16(vx);
    const __nv_bfloat16 vl0 = __float2bfloat16(vx - __bfloat162float(vh0));
    const __nv_bfloat16 vh1 = __float2bfloat16(vy);
    const __nv_bfloat16 vl1 = __float2bfloat16(vy - __bfloat162float(vh1));

    const int bh = b * HH + h;
    uint32_t* qp = (uint32_t*)(Q3 + ((size_t)bh * NN + n) * DH3 + 3 * p2);
    qp[0] = bfpack(qh0, ql0);
    qp[1] = bfpack(qh0, qh1);
    qp[2] = bfpack(ql1, qh1);
    uint32_t* kp = (uint32_t*)(K3g + ((size_t)bh * NN + n) * DH3 + 3 * p2);
    kp[0] = bfpack(kh0, kh0);
    kp[1] = bfpack(kl0, kh1);
    kp[2] = bfpack(kh1, kl1);
    uint32_t* vp = (uint32_t*)(V2 + ((size_t)bh * 2 * NN + n) * DH + p2);
    vp[0] = bfpack(vh0, vh1);
    vp[(size_t)NN * DH / 2] = bfpack(vl0, vl1);
}

// ---------------- flash K / V loaders (single stage each) ------------------
__device__ __forceinline__ void flash_load_k(
    __nv_bfloat16* ks, const __nv_bfloat16* Kbase, int kv0, int tid)
{
#pragma unroll
    for (int p = 0; p < 6; p++) {
        const int c = tid + p * 256;
        const int r = c / 24;
        const int col = (c % 24) * 8;
        __pipeline_memcpy_async(ks + r * SQ + col,
                                Kbase + (size_t)(kv0 + r) * DH3 + col, 16);
    }
    __pipeline_commit();
}
__device__ __forceinline__ void flash_load_v(
    __nv_bfloat16* vsm, const __nv_bfloat16* Vbase, int kv0, int tid)
{
#pragma unroll
    for (int p = 0; p < 4; p++) {
        const int c = tid + p * 256;
        const int r = c >> 3;                 // 0..127 (hi 0-63, lo 64-127)
        const int col = (c & 7) * 8;
        const int plane = r >> 6;
        const int n = r & 63;
        __pipeline_memcpy_async(vsm + r * SV + col,
                                Vbase + (size_t)plane * NN * DH +
                                (size_t)(kv0 + n) * DH + col, 16);
    }
    __pipeline_commit();
}

// ---------------- Flash attention: 2 blocks/SM, P in sacc registers --------
// Per tile: wait -> QK+softmax (P overwrites sacc) -> sync -> prefetch K(kt+1)
// overlapping PV -> sync -> prefetch V(kt+1). Heavy-first block order.
__global__ void __launch_bounds__(256, 2)
flash_mma(const __nv_bfloat16* __restrict__ Q3,
          const __nv_bfloat16* __restrict__ Kg3,
          const __nv_bfloat16* __restrict__ Vg2,
          __nv_bfloat16* __restrict__ ATT3)
{
    extern __shared__ char fsm[];
    __nv_bfloat16* q3s = (__nv_bfloat16*)fsm;
    __nv_bfloat16* k3s = (__nv_bfloat16*)(fsm + FOFF_K);
    __nv_bfloat16* v2s = (__nv_bfloat16*)(fsm + FOFF_V);

    const int tid = threadIdx.x;
    const int w = tid >> 5;
    const int lane = tid & 31;
    const int qt = (int)gridDim.x - 1 - (int)blockIdx.x;   // heavy first
    const int bh = blockIdx.y;
    const int q0 = qt * 128;

    const __nv_bfloat16* Qbase = Q3 + ((size_t)bh * NN + q0) * DH3;
    const __nv_bfloat16* Kbase = Kg3 + (size_t)bh * NN * DH3;
    const __nv_bfloat16* Vbase = Vg2 + (size_t)bh * 2 * NN * DH;

    const uint32_t qsb = (uint32_t)__cvta_generic_to_shared(q3s);
    const uint32_t ksb = (uint32_t)__cvta_generic_to_shared(k3s);
    const uint32_t vsb = (uint32_t)__cvta_generic_to_shared(v2s);

    flash_load_k(k3s, Kbase, 0, tid);
    flash_load_v(v2s, Vbase, 0, tid);

#pragma unroll
    for (int p = 0; p < 12; p++) {
        const int c = tid + p * 256;
        const int r = c / 24;
        const int col = (c % 24) * 8;
        *(uint4*)(q3s + r * SQ + col) =
            *(const uint4*)(Qbase + (size_t)r * DH3 + col);
    }

    const int r0 = lane >> 2;
    const int cq = lane & 3;
    const int mrow = 16 * w;
    const int grow0 = q0 + mrow + r0;
    const int grow1 = grow0 + 8;

    const int a_row = mrow + (lane & 15);
    const int a_col8 = (lane >> 4) * 8;
    const int b_rowk = ((lane >> 4) << 3) + (lane & 7);
    const int b_colk8 = ((lane >> 3) & 1) * 8;
    const int v_rowk = lane & 15;
    const int v_col8 = (lane >> 4) * 8;

    float o[8][4];
#pragma unroll
    for (int d = 0; d < 8; d++)
#pragma unroll
        for (int e = 0; e < 4; e++) o[d][e] = 0.f;
    float m0 = -1e30f, m1 = -1e30f, l0 = 0.f, l1 = 0.f;

    const int last = 2 * qt + 1;
    for (int kt = 0; kt <= last; kt++) {
        const int kv0 = kt * 64;

        __pipeline_wait_prior(0);
        __syncthreads();

        const bool active = (kv0 <= q0 + mrow + 15);
        float sacc[8][4];

        if (active) {
#pragma unroll
            for (int d = 0; d < 8; d++)
#pragma unroll
                for (int e = 0; e < 4; e++) sacc[d][e] = 0.f;

#pragma unroll
            for (int kk = 0; kk < 12; kk++) {
                uint32_t a[4];
                ldsm4(a, qsb + (uint32_t)((a_row * SQ + kk * 16 + a_col8) * 2));
#pragma unroll
                for (int np = 0; np < 4; np++) {
                    uint32_t b[4];
                    ldsm4(b, ksb + (uint32_t)(((np * 16 + b_rowk) * SQ +
                                               kk * 16 + b_colk8) * 2));
                    mma16816(sacc[2 * np], a, b);
                    mma16816(sacc[2 * np + 1], a, b + 2);
                }
            }

            if (kv0 + 63 > grow0) {
#pragma unroll
                for (int d = 0; d < 8; d++) {
                    const int col = kv0 + d * 8 + 2 * cq;
                    if (col > grow0)     sacc[d][0] = -1e30f;
                    if (col + 1 > grow0) sacc[d][1] = -1e30f;
                    if (col > grow1)     sacc[d][2] = -1e30f;
                    if (col + 1 > grow1) sacc[d][3] = -1e30f;
                }
            }
            float rm0 = sacc[0][0], rm1 = sacc[0][2];
#pragma unroll
            for (int d = 0; d < 8; d++) {
                rm0 = fmaxf(rm0, fmaxf(sacc[d][0], sacc[d][1]));
                rm1 = fmaxf(rm1, fmaxf(sacc[d][2], sacc[d][3]));
            }
            rm0 = fmaxf(rm0, __shfl_xor_sync(0xffffffffu, rm0, 1));
            rm0 = fmaxf(rm0, __shfl_xor_sync(0xffffffffu, rm0, 2));
            rm1 = fmaxf(rm1, __shfl_xor_sync(0xffffffffu, rm1, 1));
            rm1 = fmaxf(rm1, __shfl_xor_sync(0xffffffffu, rm1, 2));
            const float mn0 = fmaxf(m0, rm0);
            const float mn1 = fmaxf(m1, rm1);
            const float al0 = exp2_fast((m0 - mn0) * 1.4426950f);
            const float al1 = exp2_fast((m1 - mn1) * 1.4426950f);
            m0 = mn0; m1 = mn1;

            // softmax; packed P overwrites sacc in place:
            // [d][0]=phT [d][1]=phB [d][2]=plT [d][3]=plB
            float rs0 = 0.f, rs1 = 0.f;
#pragma unroll
            for (int d = 0; d < 8; d++) {
                const float p00 = exp2_fast((sacc[d][0] - mn0) * 1.4426950f);
                const float p01 = exp2_fast((sacc[d][1] - mn0) * 1.4426950f);
                const float p10 = exp2_fast((sacc[d][2] - mn1) * 1.4426950f);
                const float p11 = exp2_fast((sacc[d][3] - mn1) * 1.4426950f);
                rs0 += p00 + p01;
                rs1 += p10 + p11;
                const __nv_bfloat16 h00 = __float2bfloat16(p00);
                const __nv_bfloat16 g00 = __float2bfloat16(p00 - __bfloat162float(h00));
                const __nv_bfloat16 h01 = __float2bfloat16(p01);
                const __nv_bfloat16 g01 = __float2bfloat16(p01 - __bfloat162float(h01));
                const __nv_bfloat16 h10 = __float2bfloat16(p10);
                const __nv_bfloat16 g10 = __float2bfloat16(p10 - __bfloat162float(h10));
                const __nv_bfloat16 h11 = __float2bfloat16(p11);
                const __nv_bfloat16 g11 = __float2bfloat16(p11 - __bfloat162float(h11));
                sacc[d][0] = __uint_as_float(bfpack(h00, h01));
                sacc[d][1] = __uint_as_float(bfpack(h10, h11));
                sacc[d][2] = __uint_as_float(bfpack(g00, g01));
                sacc[d][3] = __uint_as_float(bfpack(g10, g11));
            }
            rs0 += __shfl_xor_sync(0xffffffffu, rs0, 1);
            rs0 += __shfl_xor_sync(0xffffffffu, rs0, 2);
            rs1 += __shfl_xor_sync(0xffffffffu, rs1, 1);
            rs1 += __shfl_xor_sync(0xffffffffu, rs1, 2);
            l0 = l0 * al0 + rs0;
            l1 = l1 * al1 + rs1;

#pragma unroll
            for (int d = 0; d < 8; d++) {
                o[d][0] *= al0; o[d][1] *= al0;
                o[d][2] *= al1; o[d][3] *= al1;
            }
        }

        // all warps done reading K -> prefetch next K tile (overlaps PV)
        __syncthreads();
        if (kt < last) flash_load_k(k3s, Kbase, kv0 + 64, tid);

        if (active) {
#pragma unroll
            for (int kk = 0; kk < 4; kk++) {
                const uint32_t ah[4] = {
                    __float_as_uint(sacc[2*kk][0]), __float_as_uint(sacc[2*kk][1]),
                    __float_as_uint(sacc[2*kk+1][0]), __float_as_uint(sacc[2*kk+1][1])};
                const uint32_t al_[4] = {
                    __float_as_uint(sacc[2*kk][2]), __float_as_uint(sacc[2*kk][3]),
                    __float_as_uint(sacc[2*kk+1][2]), __float_as_uint(sacc[2*kk+1][3])};
#pragma unroll
                for (int np = 0; np < 4; np++) {
                    uint32_t vh[4], vl[4];
                    ldsm4t(vh, vsb + (uint32_t)(((kk * 16 + v_rowk) * SV +
                                                 np * 16 + v_col8) * 2));
                    ldsm4t(vl, vsb + (uint32_t)(((64 + kk * 16 + v_rowk) * SV +
                                                 np * 16 + v_col8) * 2));
                    mma16816(o[2 * np], ah, vh);
                    mma16816(o[2 * np + 1], ah, vh + 2);
                    mma16816(o[2 * np], al_, vh);
                    mma16816(o[2 * np + 1], al_, vh + 2);
                    mma16816(o[2 * np], ah, vl);
                    mma16816(o[2 * np + 1], ah, vl + 2);
                }
            }
        }

        // all warps done reading V -> prefetch next V tile
        __syncthreads();
        if (kt < last) flash_load_v(v2s, Vbase, kv0 + 64, tid);
    }

    // epilogue: write att3 directly (pattern a: hi,lo,hi)
    {
        const int b = bh >> 4;
        const int h = bh & 15;
        const float inv0 = 1.f / l0;
        const float inv1 = 1.f / l1;
        char* orow0 = (char*)ATT3 + (size_t)(b * NN + grow0) * (K3 * 2) +
                      (h * 192 + 6 * cq) * 2;
        char* orow1 = orow0 + (size_t)8 * (K3 * 2);
#pragma unroll
        for (int d = 0; d < 8; d++) {
            const float e00 = o[d][0] * inv0;
            const float e01 = o[d][1] * inv0;
            const float e10 = o[d][2] * inv1;
            const float e11 = o[d][3] * inv1;
            const __nv_bfloat16 h00 = __float2bfloat16(e00);
            const __nv_bfloat16 g00 = __float2bfloat16(e00 - __bfloat162float(h00));
            const __nv_bfloat16 h01 = __float2bfloat16(e01);
            const __nv_bfloat16 g01 = __float2bfloat16(e01 - __bfloat162float(h01));
            const __nv_bfloat16 h10 = __float2bfloat16(e10);
            const __nv_bfloat16 g10 = __float2bfloat16(e10 - __bfloat162float(h10));
            const __nv_bfloat16 h11 = __float2bfloat16(e11);
            const __nv_bfloat16 g11 = __float2bfloat16(e11 - __bfloat162float(h11));
            uint32_t* w0 = (uint32_t*)(orow0 + 48 * d);
            w0[0] = bfpack(h00, g00);
            w0[1] = bfpack(h00, h01);
            w0[2] = bfpack(g01, h01);
            uint32_t* w1 = (uint32_t*)(orow1 + 48 * d);
            w1[0] = bfpack(h10, g10);
            w1[1] = bfpack(h10, h11);
            w1[2] = bfpack(g11, h11);
        }
    }
}

// ---------------- launch ----------------
extern "C" void kernel_launch(void* const* d_in, const int* in_sizes, int n_in,
                              void* d_out, int out_size)
{
    const float* x            = (const float*)d_in[0];
    const float* rope         = (const float*)d_in[2];
    const float* Wqkv         = (const float*)d_in[3];
    const float* Wout         = (const float*)d_in[4];
    const float* bout         = (const float*)d_in[5];
    float* out = (float*)d_out;

    float *qkv;
    __nv_bfloat16 *q3, *k3, *v2, *x3, *wqkv3, *att3, *wout3;
    cudaGetSymbolAddress((void**)&qkv, g_qkv);
    cudaGetSymbolAddress((void**)&q3,  g_q3);
    cudaGetSymbolAddress((void**)&k3,  g_k3);
    cudaGetSymbolAddress((void**)&v2,  g_v2);
    cudaGetSymbolAddress((void**)&x3,    g_x3);
    cudaGetSymbolAddress((void**)&wqkv3, g_wqkv3);
    cudaGetSymbolAddress((void**)&att3,  g_att3);
    cudaGetSymbolAddress((void**)&wout3, g_wout3);

    cudaFuncSetAttribute(gemm_mma_nt, cudaFuncAttributeMaxDynamicSharedMemorySize,
                         GEMM_SMEM);
    cudaFuncSetAttribute(flash_mma, cudaFuncAttributeMaxDynamicSharedMemorySize,
                         FLASH_SMEM);

    // merged splits (x pattern-a; Wqkv, Wout pattern-b)
    split3_all<<<(NX8 + NQ8 + NO8) / 256, 256>>>(x, x3, Wqkv, wqkv3, Wout, wout3);

    // 1) qkv = x @ Wqkv^T
    gemm_mma_nt<<<dim3(QKVC / 128, MROWS / 128), 256, GEMM_SMEM>>>(
        x3, wqkv3, (const float*)0, qkv, MROWS, QKVC, K3);

    // 2) RoPE + split -> Q3, K3, V2 (hi/lo planes)
    rope3_kernel<<<(BB * NN * HH * 32 + 255) / 256, 256>>>(qkv, rope, q3, k3, v2);

    // 3) causal flash attention -> att3 (pre-split for out-proj)
    flash_mma<<<dim3(NN / 128, BB * HH), 256, FLASH_SMEM>>>(q3, k3, v2, att3);

    // 4) out = att @ Wout^T + bias (fused)
    gemm_mma_nt<<<dim3(OUTC / 128, MROWS / 128), 256, GEMM_SMEM>>>(
        att3, wout3, bout, out, MROWS, OUTC, K3);
}